// round 11
// baseline (speedup 1.0000x reference)
#include <cuda_runtime.h>
#include <cuda_bf16.h>
#include <cstdint>
#include <cstddef>

// ---------------- problem constants ----------------
#define NN_NODES 10000
#define IN_C     256
#define C1       128
#define OUT_C    64
#define NE       640000
#define KPAD     10048          // padded K for B (zero-filled)
#define BKC      32             // K per mainloop chunk
#define CH1      313            // ceil(10000/32)
#define NTILES   314            // 157 m-blocks x 2 n-blocks
#define GWORK    ((long)NTILES * CH1)   // 98282 chunk-units
#define NCTAS    296            // 148 SMs x 2 CTAs/SM, one wave

// ---------------- PTX helpers ----------------
__device__ __forceinline__ uint32_t smem_u32(const void* p) {
    uint32_t a;
    asm("{ .reg .u64 t; cvta.to.shared.u64 t, %1; cvt.u32.u64 %0, t; }" : "=r"(a) : "l"(p));
    return a;
}
__device__ __forceinline__ void ldm_x4(uint32_t& r0, uint32_t& r1, uint32_t& r2, uint32_t& r3,
                                       uint32_t addr) {
    asm volatile("ldmatrix.sync.aligned.m8n8.x4.shared.b16 {%0,%1,%2,%3}, [%4];"
                 : "=r"(r0), "=r"(r1), "=r"(r2), "=r"(r3) : "r"(addr));
}
__device__ __forceinline__ void mma16816(float* d, const uint32_t* a, const uint32_t* b) {
    asm volatile("mma.sync.aligned.m16n8k16.row.col.f32.bf16.bf16.f32 "
                 "{%0,%1,%2,%3}, {%4,%5,%6,%7}, {%8,%9}, {%0,%1,%2,%3};"
                 : "+f"(d[0]), "+f"(d[1]), "+f"(d[2]), "+f"(d[3])
                 : "r"(a[0]), "r"(a[1]), "r"(a[2]), "r"(a[3]), "r"(b[0]), "r"(b[1]));
}
#define CP16(dst, src) \
    asm volatile("cp.async.cg.shared.global [%0], [%1], 16;" :: "r"(dst), "l"(src))
#define CP16Z(dst, src, sz) \
    asm volatile("cp.async.cg.shared.global [%0], [%1], 16, %2;" :: "r"(dst), "l"(src), "r"(sz))
#define CP_COMMIT() asm volatile("cp.async.commit_group;")
#define CP_WAIT1()  asm volatile("cp.async.wait_group 1;")
#define CP_WAIT0()  asm volatile("cp.async.wait_group 0;")

// ---------------- scratch globals ----------------
__device__ float g_h   [NN_NODES * IN_C];   // zeroed, atomically accumulated, then final h
__device__ float g_tx1 [NN_NODES * IN_C];
__device__ float g_h2  [NN_NODES * C1];
__device__ float g_tx2 [NN_NODES * C1];
__device__ int   g_outdeg[NN_NODES];
__device__ int   g_indeg [NN_NODES];
__device__ float g_dinv  [NN_NODES];
__device__ int   g_rowstart[NN_NODES + 1];
__device__ int   g_cursor  [NN_NODES];
__device__ int   g_srcs [NE];
__device__ float g_ws   [NE];
__device__ __nv_bfloat16 g_BT_hi[256 * KPAD];   // Wt^T split-hi, [n][k]
__device__ __nv_bfloat16 g_BT_lo[256 * KPAD];   // Wt^T split-lo

// ---------------- preprocessing kernels ----------------
__global__ void k_zero_deg(int n) {
    int i = blockIdx.x * blockDim.x + threadIdx.x;
    if (i < n) { g_outdeg[i] = 0; g_indeg[i] = 0; }
}
__global__ void k_zeroH() {
    int i = blockIdx.x * blockDim.x + threadIdx.x;
    if (i < NN_NODES * IN_C / 4)
        reinterpret_cast<float4*>(g_h)[i] = make_float4(0.f, 0.f, 0.f, 0.f);
}
__global__ void k_count(const int* __restrict__ ei) {
    int e = blockIdx.x * blockDim.x + threadIdx.x;
    if (e < NE) {
        atomicAdd(&g_outdeg[ei[e]], 1);
        atomicAdd(&g_indeg[ei[NE + e]], 1);
    }
}
__global__ void k_dinv(int n) {
    int i = blockIdx.x * blockDim.x + threadIdx.x;
    if (i < n) {
        int d = g_outdeg[i];
        g_dinv[i] = (d > 0) ? rsqrtf((float)d) : 0.0f;
    }
}
// one-pass scan: each thread owns 10 rows
__global__ void k_scan(int n) {
    __shared__ int sh[1024];
    int t = threadIdx.x;
    const int per = 10;
    int base = t * per;
    int loc[10];
    int s = 0;
#pragma unroll
    for (int i = 0; i < per; i++) {
        int idx = base + i;
        int v = (idx < n) ? g_indeg[idx] : 0;
        loc[i] = s; s += v;
    }
    sh[t] = s;
    __syncthreads();
    for (int off = 1; off < 1024; off <<= 1) {
        int v = (t >= off) ? sh[t - off] : 0;
        __syncthreads();
        sh[t] += v;
        __syncthreads();
    }
    int bb = (t > 0) ? sh[t - 1] : 0;
#pragma unroll
    for (int i = 0; i < per; i++) {
        int idx = base + i;
        if (idx < n) { int v = bb + loc[i]; g_rowstart[idx] = v; g_cursor[idx] = v; }
    }
    if (t == 1023) g_rowstart[n] = sh[1023];
}
__global__ void k_bucket(const int* __restrict__ ei) {
    int e = blockIdx.x * blockDim.x + threadIdx.x;
    if (e < NE) {
        int s = ei[e];
        int d = ei[NE + e];
        int pos = atomicAdd(&g_cursor[d], 1);
        g_srcs[pos] = s;
        g_ws[pos]   = -g_dinv[s] * g_dinv[d];
    }
}

// Wt [10000,256] fp32 -> transposed bf16 hi/lo [256][KPAD]
__global__ void k_convW(const float* __restrict__ Wt) {
    __shared__ float tile[32][33];
    int bx = blockIdx.x, by = blockIdx.y;
    int tx = threadIdx.x, ty = threadIdx.y;
    int gk = bx * 32 + ty;
    int gn = by * 32 + tx;
    tile[ty][tx] = (gk < NN_NODES) ? Wt[(size_t)gk * 256 + gn] : 0.0f;
    __syncthreads();
    int n = by * 32 + ty;
    int k = bx * 32 + tx;
    float v = tile[tx][ty];
    __nv_bfloat16 hi = __float2bfloat16(v);
    __nv_bfloat16 lo = __float2bfloat16(v - __bfloat162float(hi));
    g_BT_hi[(size_t)n * KPAD + k] = hi;
    g_BT_lo[(size_t)n * KPAD + k] = lo;
}

// ---------------- GEMM1 via mma.sync bf16 (3-term split) --------------------
// Balanced flat partition (296 CTAs) + 3-stage pure-cp.async pipeline.
// A stored as raw fp32 in smem (pitch 160B, conflict-free for frag LDS.64);
// hi/lo bf16 split happens at consume time (truncation split, overlaps MMA).
// Stage: A fp32 @0 (64x160B=10240) | Bhi @10240 (128x80B) | Blo @20480.
#define AP       160
#define STG      30720
#define NSTG     3
#define G1_SMEM  (NSTG * STG)
#define PITCH    80

__global__ void __launch_bounds__(256, 2)
k_gemm1_mma(const float* __restrict__ X, float* __restrict__ P) {
    extern __shared__ char smem[];
    const uint32_t sb = smem_u32(smem);
    const int tid  = threadIdx.x;
    const int wid  = tid >> 5, lane = tid & 31;
    const int warp_m = (wid >> 2) * 32;     // 2 m-warps
    const int warp_n = (wid & 3) * 32;      // 4 n-warps

    // B loader coords: 128 rows x 2 threads/row
    const int blr = tid >> 1;
    const int blh = tid & 1;

    // B ldmatrix lane offsets
    const int La     = lane & 7;
    const int b_noff = (lane >> 4) * 8 + La;
    const int b_koff = ((lane >> 3) & 1) * 8;

    const char* bhsrc = (const char*)g_BT_hi;
    const char* blsrc = (const char*)g_BT_lo;
    const size_t brow = (size_t)KPAD * 2;

    float acc[2][4][4];

    long g  = (long)blockIdx.x * GWORK / NCTAS;
    long g1 = (long)(blockIdx.x + 1) * GWORK / NCTAS;

    while (g < g1) {
        const int t   = (int)(g / CH1);
        const int cst = (int)(g % CH1);
        int cend = CH1;
        {
            long avail = g1 - g;
            if ((long)(CH1 - cst) > avail) cend = cst + (int)avail;
        }
        const int m0  = (t >> 1) * 64;
        const int n0g = (t & 1) * 128;

#pragma unroll
        for (int i = 0; i < 2; i++)
#pragma unroll
            for (int j = 0; j < 4; j++)
#pragma unroll
                for (int q = 0; q < 4; q++) acc[i][j][q] = 0.0f;

#define ISSUE(c, st_) do {                                                       \
        int k0 = (c) * BKC;                                                      \
        uint32_t stg_ = sb + (uint32_t)(st_) * STG;                              \
        _Pragma("unroll")                                                        \
        for (int i_ = 0; i_ < 2; ++i_) {                                         \
            int u_ = tid * 2 + i_;                                               \
            int row_ = u_ >> 3, p_ = u_ & 7;                                     \
            const char* src_ = (const char*)(X + (size_t)(m0 + row_) * NN_NODES  \
                                             + k0 + p_ * 4);                     \
            uint32_t dst_ = stg_ + (uint32_t)(row_ * AP + p_ * 16);              \
            int sz_ = ((m0 + row_) < NN_NODES && (k0 + p_ * 4) < NN_NODES) ? 16 : 0; \
            CP16Z(dst_, src_, sz_);                                              \
        }                                                                        \
        {                                                                        \
            uint32_t dsth = stg_ + 10240u + (uint32_t)(blr * PITCH + blh * 32);  \
            const char* sh_ = bhsrc + (size_t)(n0g + blr) * brow + k0 * 2 + blh * 32; \
            const char* sl_ = blsrc + (size_t)(n0g + blr) * brow + k0 * 2 + blh * 32; \
            CP16(dsth,          sh_);   CP16(dsth + 16,          sh_ + 16);      \
            CP16(dsth + 10240u, sl_);   CP16(dsth + 10240u + 16, sl_ + 16);      \
        }                                                                        \
    } while (0)

        // prologue: issue first two stages
        ISSUE(cst, 0); CP_COMMIT();
        if (cst + 1 < cend) ISSUE(cst + 1, 1);
        CP_COMMIT();

        for (int c = cst; c < cend; ++c) {
            const int i = c - cst;
            CP_WAIT1();
            __syncthreads();
            if (c + 2 < cend) ISSUE(c + 2, (i + 2) % 3);
            CP_COMMIT();

            const uint32_t As = sb + (uint32_t)(i % 3) * STG;
            const uint32_t Bs = As + 10240u;
#pragma unroll
            for (int ks = 0; ks < 2; ++ks) {
                const int kb = ks * 16;
                uint32_t ah[2][4], al[2][4], bh[2][4], bl[2][4];
                // A frags: LDS fp32 pairs in a-frag layout, truncation split
#pragma unroll
                for (int mt = 0; mt < 2; ++mt)
#pragma unroll
                    for (int j = 0; j < 4; ++j) {
                        int row = warp_m + mt * 16 + ((j & 1) << 3) + (lane >> 2);
                        int kk  = kb + ((j >> 1) << 3) + ((lane & 3) << 1);
                        float x0, x1;
                        asm volatile("ld.shared.v2.f32 {%0,%1}, [%2];"
                                     : "=f"(x0), "=f"(x1)
                                     : "r"(As + (uint32_t)(row * AP + kk * 4)));
                        uint32_t u0 = __float_as_uint(x0), u1 = __float_as_uint(x1);
                        uint32_t hi;
                        asm("prmt.b32 %0, %1, %2, 0x7632;" : "=r"(hi) : "r"(u0), "r"(u1));
                        float h0 = __uint_as_float(u0 & 0xFFFF0000u);
                        float h1 = __uint_as_float(u1 & 0xFFFF0000u);
                        float l0 = x0 - h0, l1 = x1 - h1;
                        uint32_t lo;
                        asm("cvt.rn.bf16x2.f32 %0, %1, %2;" : "=r"(lo) : "f"(l1), "f"(l0));
                        ah[mt][j] = hi;
                        al[mt][j] = lo;
                    }
                // B frags via ldmatrix (unchanged layout)
#pragma unroll
                for (int bb = 0; bb < 2; ++bb) {
                    uint32_t rb = Bs + (uint32_t)((warp_n + bb * 16 + b_noff) * PITCH
                                                  + (kb + b_koff) * 2);
                    ldm_x4(bh[bb][0], bh[bb][1], bh[bb][2], bh[bb][3], rb);
                    ldm_x4(bl[bb][0], bl[bb][1], bl[bb][2], bl[bb][3], rb + 10240u);
                }
#pragma unroll
                for (int mt = 0; mt < 2; ++mt)
#pragma unroll
                    for (int nt = 0; nt < 4; ++nt)
                        mma16816(acc[mt][nt], ah[mt], &bh[nt >> 1][(nt & 1) * 2]);
#pragma unroll
                for (int mt = 0; mt < 2; ++mt)
#pragma unroll
                    for (int nt = 0; nt < 4; ++nt)
                        mma16816(acc[mt][nt], ah[mt], &bl[nt >> 1][(nt & 1) * 2]);
#pragma unroll
                for (int mt = 0; mt < 2; ++mt)
#pragma unroll
                    for (int nt = 0; nt < 4; ++nt)
                        mma16816(acc[mt][nt], al[mt], &bh[nt >> 1][(nt & 1) * 2]);
            }
        }
#undef ISSUE

        // drain before reusing stages in the next segment
        CP_WAIT0();
        __syncthreads();

        // segment epilogue: accumulate partial into pre-zeroed P
        {
            const int gg = lane >> 2;
            const int t2 = (lane & 3) * 2;
#pragma unroll
            for (int nt = 0; nt < 4; ++nt) {
                int n = n0g + warp_n + nt * 8 + t2;
#pragma unroll
                for (int mt = 0; mt < 2; ++mt) {
                    int ma = m0 + warp_m + mt * 16 + gg;
                    if (ma < NN_NODES) {
                        atomicAdd(&P[(size_t)ma * 256 + n],     acc[mt][nt][0]);
                        atomicAdd(&P[(size_t)ma * 256 + n + 1], acc[mt][nt][1]);
                    }
                    int mb = ma + 8;
                    if (mb < NN_NODES) {
                        atomicAdd(&P[(size_t)mb * 256 + n],     acc[mt][nt][2]);
                        atomicAdd(&P[(size_t)mb * 256 + n + 1], acc[mt][nt][3]);
                    }
                }
            }
        }
        g += (long)(cend - cst);
    }
}

// h = relu(h + bias)  (in place)
__global__ void k_combine(const float* __restrict__ bt, float* __restrict__ H) {
    int i = blockIdx.x * blockDim.x + threadIdx.x;   // float4 index
    if (i < NN_NODES * IN_C / 4) {
        float4 a = reinterpret_cast<const float4*>(H)[i];
        int col = (i * 4) & 255;
        float4 o;
        o.x = fmaxf(a.x + bt[col + 0], 0.f);
        o.y = fmaxf(a.y + bt[col + 1], 0.f);
        o.z = fmaxf(a.z + bt[col + 2], 0.f);
        o.w = fmaxf(a.w + bt[col + 3], 0.f);
        reinterpret_cast<float4*>(H)[i] = o;
    }
}

// ---------------- SpMM: one block per dst row, one thread per channel -------
template <int CH>
__global__ void __launch_bounds__(CH) k_spmm(const float* __restrict__ h,
                                             float* __restrict__ tx) {
    int d = blockIdx.x;
    int c = threadIdx.x;
    int beg = g_rowstart[d];
    int end = g_rowstart[d + 1];
    float acc = 0.0f;
    int j = beg;
    for (; j + 4 <= end; j += 4) {
        int   s0 = g_srcs[j],   s1 = g_srcs[j+1], s2 = g_srcs[j+2], s3 = g_srcs[j+3];
        float w0 = g_ws[j],     w1 = g_ws[j+1],   w2 = g_ws[j+2],   w3 = g_ws[j+3];
        float h0 = h[(size_t)s0 * CH + c];
        float h1 = h[(size_t)s1 * CH + c];
        float h2 = h[(size_t)s2 * CH + c];
        float h3 = h[(size_t)s3 * CH + c];
        acc += w0 * h0; acc += w1 * h1; acc += w2 * h2; acc += w3 * h3;
    }
    for (; j < end; ++j)
        acc += g_ws[j] * h[(size_t)g_srcs[j] * CH + c];
    tx[(size_t)d * CH + c] = acc;
}

// ---------------- SIMT SGEMM for gemm2 --------------------------------------
template <int BM, int BN, int BK, int TM, int TN, bool RELU>
__global__ void __launch_bounds__((BM / TM) * (BN / TN))
k_gemm(const float* __restrict__ A1, const float* __restrict__ B1,
       const float* __restrict__ A2, const float* __restrict__ B2,
       const float* __restrict__ bias, float* __restrict__ C,
       int M, int N, int K) {
    constexpr int NT = (BM / TM) * (BN / TN);
    __shared__ float As[BK][BM];
    __shared__ float Bs[BK][BN];

    const int tid = threadIdx.x;
    const int m0 = blockIdx.y * BM;
    const int n0 = blockIdx.x * BN;
    const int tr = tid / (BN / TN);
    const int tc = tid % (BN / TN);
    const int rowBase = tr * TM;
    const int colBase = tc * TN;

    float acc[TM][TN];
#pragma unroll
    for (int i = 0; i < TM; i++)
#pragma unroll
        for (int j = 0; j < TN; j++) acc[i][j] = 0.0f;

    const int nphase = (A2 != nullptr) ? 2 : 1;
    for (int phase = 0; phase < nphase; ++phase) {
        const float* __restrict__ A = phase ? A2 : A1;
        const float* __restrict__ B = phase ? B2 : B1;
        for (int k0 = 0; k0 < K; k0 += BK) {
            constexpr int AIT = (BM * BK / 4) / NT;
#pragma unroll
            for (int it = 0; it < AIT; ++it) {
                int idx = tid + it * NT;
                int ar = idx / (BK / 4);
                int akg = idx % (BK / 4);
                int grow = m0 + ar;
                float4 f = make_float4(0.f, 0.f, 0.f, 0.f);
                if (grow < M)
                    f = *reinterpret_cast<const float4*>(A + (size_t)grow * K + k0 + akg * 4);
                As[akg * 4 + 0][ar] = f.x;
                As[akg * 4 + 1][ar] = f.y;
                As[akg * 4 + 2][ar] = f.z;
                As[akg * 4 + 3][ar] = f.w;
            }
            constexpr int BIT = (BK * BN) / NT;
#pragma unroll
            for (int it = 0; it < BIT; ++it) {
                int idx = tid + it * NT;
                int br = idx / BN;
                int bc = idx % BN;
                Bs[br][bc] = B[(size_t)(k0 + br) * N + n0 + bc];
            }
            __syncthreads();
#pragma unroll
            for (int k = 0; k < BK; k++) {
                float ra[TM], rb[TN];
#pragma unroll
                for (int i = 0; i < TM; i++) ra[i] = As[k][rowBase + i];
#pragma unroll
                for (int j = 0; j < TN; j++) rb[j] = Bs[k][colBase + j];
#pragma unroll
                for (int i = 0; i < TM; i++)
#pragma unroll
                    for (int j = 0; j < TN; j++)
                        acc[i][j] += ra[i] * rb[j];
            }
            __syncthreads();
        }
    }

    float bv[TN];
#pragma unroll
    for (int j = 0; j < TN; j++) bv[j] = bias[n0 + colBase + j];

#pragma unroll
    for (int i = 0; i < TM; i++) {
        int grow = m0 + rowBase + i;
        if (grow < M) {
            float4 o;
            float v0 = acc[i][0] + bv[0];
            float v1 = acc[i][1] + bv[1];
            float v2 = acc[i][2] + bv[2];
            float v3 = acc[i][3] + bv[3];
            if (RELU) {
                v0 = fmaxf(v0, 0.f); v1 = fmaxf(v1, 0.f);
                v2 = fmaxf(v2, 0.f); v3 = fmaxf(v3, 0.f);
            }
            o.x = v0; o.y = v1; o.z = v2; o.w = v3;
            *reinterpret_cast<float4*>(C + (size_t)grow * N + n0 + colBase) = o;
        }
    }
}

// ---------------- fused mu+logstd GEMM (shared A tiles) ---------------------
__global__ void __launch_bounds__(256)
k_gemm_dual(const float* __restrict__ A1, const float* __restrict__ A2,
            const float* __restrict__ Bm1, const float* __restrict__ Bm2,
            const float* __restrict__ Bl1, const float* __restrict__ Bl2,
            const float* __restrict__ bm, const float* __restrict__ bl,
            float* __restrict__ Cm, float* __restrict__ Cl) {
    __shared__ float As[8][64];
    __shared__ float Bmu[8][64];
    __shared__ float Bls[8][64];
    const int tid = threadIdx.x;
    const int m0 = blockIdx.x * 64;
    const int tr = tid >> 4, tc = tid & 15;

    float am[4][4], al_[4][4];
#pragma unroll
    for (int i = 0; i < 4; i++)
#pragma unroll
        for (int j = 0; j < 4; j++) { am[i][j] = 0.f; al_[i][j] = 0.f; }

    for (int ph = 0; ph < 2; ++ph) {
        const float* A   = ph ? A2  : A1;
        const float* Bm_ = ph ? Bm2 : Bm1;
        const float* Bl_ = ph ? Bl2 : Bl1;
        for (int k0 = 0; k0 < C1; k0 += 8) {
#pragma unroll
            for (int it = 0; it < 2; ++it) {
                int idx = tid + it * 256;
                int ar = idx >> 3, ak = idx & 7;
                int gm = m0 + ar;
                As[ak][ar] = (gm < NN_NODES) ? A[(size_t)gm * C1 + k0 + ak] : 0.f;
            }
#pragma unroll
            for (int it = 0; it < 2; ++it) {
                int idx = tid + it * 256;
                int bk = idx >> 6, bc = idx & 63;
                Bmu[bk][bc] = Bm_[(size_t)(k0 + bk) * 64 + bc];
                Bls[bk][bc] = Bl_[(size_t)(k0 + bk) * 64 + bc];
            }
            __syncthreads();
#pragma unroll
            for (int k = 0; k < 8; ++k) {
                float ra[4], rm[4], rl[4];
#pragma unroll
                for (int i = 0; i < 4; i++) {
                    ra[i] = As[k][tr * 4 + i];
                    rm[i] = Bmu[k][tc * 4 + i];
                    rl[i] = Bls[k][tc * 4 + i];
                }
#pragma unroll
                for (int i = 0; i < 4; i++)
#pragma unroll
                    for (int j = 0; j < 4; j++) {
                        am[i][j]  += ra[i] * rm[j];
                        al_[i][j] += ra[i] * rl[j];
                    }
            }
            __syncthreads();
        }
    }

    float bvm[4], bvl[4];
#pragma unroll
    for (int j = 0; j < 4; j++) { bvm[j] = bm[tc * 4 + j]; bvl[j] = bl[tc * 4 + j]; }
#pragma unroll
    for (int i = 0; i < 4; i++) {
        int gm = m0 + tr * 4 + i;
        if (gm < NN_NODES) {
            float4 om, ol;
            om.x = am[i][0] + bvm[0]; om.y = am[i][1] + bvm[1];
            om.z = am[i][2] + bvm[2]; om.w = am[i][3] + bvm[3];
            ol.x = al_[i][0] + bvl[0]; ol.y = al_[i][1] + bvl[1];
            ol.z = al_[i][2] + bvl[2]; ol.w = al_[i][3] + bvl[3];
            *reinterpret_cast<float4*>(Cm + (size_t)gm * 64 + tc * 4) = om;
            *reinterpret_cast<float4*>(Cl + (size_t)gm * 64 + tc * 4) = ol;
        }
    }
}

// ---------------- launcher --------------------------------------------------
extern "C" void kernel_launch(void* const* d_in, const int* in_sizes, int n_in,
                              void* d_out, int out_size) {
    const float* x    = (const float*)d_in[0];
    const int*   ei   = (const int*)d_in[1];
    const float* Wt   = (const float*)d_in[2];
    const float* bt   = (const float*)d_in[3];
    const float* W0_1 = (const float*)d_in[4];
    const float* W1_1 = (const float*)d_in[5];
    const float* b1   = (const float*)d_in[6];
    const float* W0mu = (const float*)d_in[7];
    const float* W1mu = (const float*)d_in[8];
    const float* bmu  = (const float*)d_in[9];
    const float* W0ls = (const float*)d_in[10];
    const float* W1ls = (const float*)d_in[11];
    const float* bls  = (const float*)d_in[12];
    float* out = (float*)d_out;

    float *h, *tx1, *h2, *tx2;
    cudaGetSymbolAddress((void**)&h,   g_h);
    cudaGetSymbolAddress((void**)&tx1, g_tx1);
    cudaGetSymbolAddress((void**)&h2,  g_h2);
    cudaGetSymbolAddress((void**)&tx2, g_tx2);

    cudaFuncSetAttribute(k_gemm1_mma, cudaFuncAttributeMaxDynamicSharedMemorySize, G1_SMEM);

    const int TPB = 256;

    // GEMM1 deps first; k_gemm1_mma stays at launch index 3 (ncu samples it)
    {
        dim3 grid(KPAD / 32, 256 / 32), blk(32, 32);
        k_convW<<<grid, blk>>>(Wt);                                  // 0
    }
    k_zeroH<<<(NN_NODES * IN_C / 4 + TPB - 1) / TPB, TPB>>>();       // 1
    k_zero_deg<<<(NN_NODES + TPB - 1) / TPB, TPB>>>(NN_NODES);       // 2
    k_gemm1_mma<<<NCTAS, 256, G1_SMEM>>>(x, h);                      // 3
    k_combine<<<(NN_NODES * IN_C / 4 + TPB - 1) / TPB, TPB>>>(bt, h);
    k_count<<<(NE + TPB - 1) / TPB, TPB>>>(ei);
    k_dinv<<<(NN_NODES + TPB - 1) / TPB, TPB>>>(NN_NODES);
    k_scan<<<1, 1024>>>(NN_NODES);
    k_bucket<<<(NE + TPB - 1) / TPB, TPB>>>(ei);

    // tx1 = L_hat @ h
    k_spmm<IN_C><<<NN_NODES, IN_C>>>(h, tx1);

    // h2 = relu(h @ W0_1 + tx1 @ W1_1 + b1)
    {
        dim3 grid(C1 / 64, (NN_NODES + 127) / 128);
        k_gemm<128, 64, 8, 8, 4, true><<<grid, 256>>>(
            h, W0_1, tx1, W1_1, b1, h2, NN_NODES, C1, IN_C);
    }
    // tx2 = L_hat @ h2
    k_spmm<C1><<<NN_NODES, C1>>>(h2, tx2);

    // mu / logstd fused
    k_gemm_dual<<<157, 256>>>(h2, tx2, W0mu, W1mu, W0ls, W1ls,
                              bmu, bls, out, out + (size_t)NN_NODES * OUT_C);
}

// round 12
// speedup vs baseline: 1.0438x; 1.0438x over previous
#include <cuda_runtime.h>
#include <cuda_bf16.h>
#include <cstdint>
#include <cstddef>

// ---------------- problem constants ----------------
#define NN_NODES 10000
#define IN_C     256
#define C1       128
#define OUT_C    64
#define NE       640000
#define KPAD     10048          // padded K for B (zero-filled)
#define BKC      32             // K per mainloop chunk
#define CH1      313            // ceil(10000/32)
#define NTILES   158            // 79 m-blocks (128 rows) x 2 n-blocks (128 cols)
#define GWORK    ((long)NTILES * CH1)   // 49454 chunk-units
#define NCTAS    296            // 148 SMs x 2 CTAs/SM, one wave

// ---------------- PTX helpers ----------------
__device__ __forceinline__ uint32_t smem_u32(const void* p) {
    uint32_t a;
    asm("{ .reg .u64 t; cvta.to.shared.u64 t, %1; cvt.u32.u64 %0, t; }" : "=r"(a) : "l"(p));
    return a;
}
__device__ __forceinline__ void ldm_x4(uint32_t& r0, uint32_t& r1, uint32_t& r2, uint32_t& r3,
                                       uint32_t addr) {
    asm volatile("ldmatrix.sync.aligned.m8n8.x4.shared.b16 {%0,%1,%2,%3}, [%4];"
                 : "=r"(r0), "=r"(r1), "=r"(r2), "=r"(r3) : "r"(addr));
}
__device__ __forceinline__ void mma16816(float* d, const uint32_t* a, const uint32_t* b) {
    asm volatile("mma.sync.aligned.m16n8k16.row.col.f32.bf16.bf16.f32 "
                 "{%0,%1,%2,%3}, {%4,%5,%6,%7}, {%8,%9}, {%0,%1,%2,%3};"
                 : "+f"(d[0]), "+f"(d[1]), "+f"(d[2]), "+f"(d[3])
                 : "r"(a[0]), "r"(a[1]), "r"(a[2]), "r"(a[3]), "r"(b[0]), "r"(b[1]));
}
#define CP16(dst, src) \
    asm volatile("cp.async.cg.shared.global [%0], [%1], 16;" :: "r"(dst), "l"(src))
#define CP16Z(dst, src, sz) \
    asm volatile("cp.async.cg.shared.global [%0], [%1], 16, %2;" :: "r"(dst), "l"(src), "r"(sz))
#define CP_COMMIT() asm volatile("cp.async.commit_group;")
#define CP_WAIT0()  asm volatile("cp.async.wait_group 0;")

// ---------------- scratch globals ----------------
__device__ float g_h   [NN_NODES * IN_C];   // zeroed, atomically accumulated, then final h
__device__ float g_tx1 [NN_NODES * IN_C];
__device__ float g_h2  [NN_NODES * C1];
__device__ float g_tx2 [NN_NODES * C1];
__device__ int   g_outdeg[NN_NODES];
__device__ int   g_indeg [NN_NODES];
__device__ float g_dinv  [NN_NODES];
__device__ int   g_rowstart[NN_NODES + 1];
__device__ int   g_cursor  [NN_NODES];
__device__ int   g_srcs [NE];
__device__ float g_ws   [NE];
__device__ __nv_bfloat16 g_BT_hi[256 * KPAD];   // Wt^T split-hi, [n][k]
__device__ __nv_bfloat16 g_BT_lo[256 * KPAD];   // Wt^T split-lo

// ---------------- preprocessing kernels ----------------
__global__ void k_zero_deg(int n) {
    int i = blockIdx.x * blockDim.x + threadIdx.x;
    if (i < n) { g_outdeg[i] = 0; g_indeg[i] = 0; }
}
__global__ void k_zeroH() {
    int i = blockIdx.x * blockDim.x + threadIdx.x;
    if (i < NN_NODES * IN_C / 4)
        reinterpret_cast<float4*>(g_h)[i] = make_float4(0.f, 0.f, 0.f, 0.f);
}
__global__ void k_count(const int* __restrict__ ei) {
    int e = blockIdx.x * blockDim.x + threadIdx.x;
    if (e < NE) {
        atomicAdd(&g_outdeg[ei[e]], 1);
        atomicAdd(&g_indeg[ei[NE + e]], 1);
    }
}
__global__ void k_dinv(int n) {
    int i = blockIdx.x * blockDim.x + threadIdx.x;
    if (i < n) {
        int d = g_outdeg[i];
        g_dinv[i] = (d > 0) ? rsqrtf((float)d) : 0.0f;
    }
}
// one-pass scan: each thread owns 10 rows
__global__ void k_scan(int n) {
    __shared__ int sh[1024];
    int t = threadIdx.x;
    const int per = 10;
    int base = t * per;
    int loc[10];
    int s = 0;
#pragma unroll
    for (int i = 0; i < per; i++) {
        int idx = base + i;
        int v = (idx < n) ? g_indeg[idx] : 0;
        loc[i] = s; s += v;
    }
    sh[t] = s;
    __syncthreads();
    for (int off = 1; off < 1024; off <<= 1) {
        int v = (t >= off) ? sh[t - off] : 0;
        __syncthreads();
        sh[t] += v;
        __syncthreads();
    }
    int bb = (t > 0) ? sh[t - 1] : 0;
#pragma unroll
    for (int i = 0; i < per; i++) {
        int idx = base + i;
        if (idx < n) { int v = bb + loc[i]; g_rowstart[idx] = v; g_cursor[idx] = v; }
    }
    if (t == 1023) g_rowstart[n] = sh[1023];
}
__global__ void k_bucket(const int* __restrict__ ei) {
    int e = blockIdx.x * blockDim.x + threadIdx.x;
    if (e < NE) {
        int s = ei[e];
        int d = ei[NE + e];
        int pos = atomicAdd(&g_cursor[d], 1);
        g_srcs[pos] = s;
        g_ws[pos]   = -g_dinv[s] * g_dinv[d];
    }
}

// Wt [10000,256] fp32 -> transposed bf16 hi/lo [256][KPAD]
__global__ void k_convW(const float* __restrict__ Wt) {
    __shared__ float tile[32][33];
    int bx = blockIdx.x, by = blockIdx.y;
    int tx = threadIdx.x, ty = threadIdx.y;
    int gk = bx * 32 + ty;
    int gn = by * 32 + tx;
    tile[ty][tx] = (gk < NN_NODES) ? Wt[(size_t)gk * 256 + gn] : 0.0f;
    __syncthreads();
    int n = by * 32 + ty;
    int k = bx * 32 + tx;
    float v = tile[tx][ty];
    __nv_bfloat16 hi = __float2bfloat16(v);
    __nv_bfloat16 lo = __float2bfloat16(v - __bfloat162float(hi));
    g_BT_hi[(size_t)n * KPAD + k] = hi;
    g_BT_lo[(size_t)n * KPAD + k] = lo;
}

// ---------------- GEMM1 via mma.sync bf16 (3-term split) --------------------
// Balanced flat partition (296 CTAs, 158 tiles of 128x128) + 2-stage pure
// cp.async pipeline. A in smem as raw fp32 (pitch 160B, conflict-free LDS.64);
// A hi/lo split at consume time (truncation; verified R10). Warp tile 32x64
// (4m x 2n warps) amortizes frag loads: A redundancy 2x, split cost /48 MMAs.
// Stage: A fp32 @0 (128x160B=20480) | Bhi @20480 (128x80B) | Blo @30720.
#define AP       160
#define STG      40960
#define G1_SMEM  (2 * STG)
#define PITCH    80

__global__ void __launch_bounds__(256, 2)
k_gemm1_mma(const float* __restrict__ X, float* __restrict__ P) {
    extern __shared__ char smem[];
    const uint32_t sb = smem_u32(smem);
    const int tid  = threadIdx.x;
    const int wid  = tid >> 5, lane = tid & 31;
    const int warp_m = (wid >> 1) * 32;     // 4 m-warps
    const int warp_n = (wid & 1) * 64;      // 2 n-warps

    // B loader coords: 128 rows x 2 threads/row
    const int blr = tid >> 1;
    const int blh = tid & 1;

    // B ldmatrix lane offsets
    const int La     = lane & 7;
    const int b_noff = (lane >> 4) * 8 + La;
    const int b_koff = ((lane >> 3) & 1) * 8;

    const char* bhsrc = (const char*)g_BT_hi;
    const char* blsrc = (const char*)g_BT_lo;
    const size_t brow = (size_t)KPAD * 2;

    float acc[2][8][4];

    long g  = (long)blockIdx.x * GWORK / NCTAS;
    long g1 = (long)(blockIdx.x + 1) * GWORK / NCTAS;

    while (g < g1) {
        const int t   = (int)(g / CH1);
        const int cst = (int)(g % CH1);
        int cend = CH1;
        {
            long avail = g1 - g;
            if ((long)(CH1 - cst) > avail) cend = cst + (int)avail;
        }
        const int m0  = (t >> 1) * 128;
        const int n0g = (t & 1) * 128;

#pragma unroll
        for (int i = 0; i < 2; i++)
#pragma unroll
            for (int j = 0; j < 8; j++)
#pragma unroll
                for (int q = 0; q < 4; q++) acc[i][j][q] = 0.0f;

#define ISSUE(c, st_) do {                                                       \
        int k0 = (c) * BKC;                                                      \
        uint32_t stg_ = sb + (uint32_t)(st_) * STG;                              \
        _Pragma("unroll")                                                        \
        for (int i_ = 0; i_ < 4; ++i_) {                                         \
            int u_ = tid * 4 + i_;                                               \
            int row_ = u_ >> 3, p_ = u_ & 7;                                     \
            const char* src_ = (const char*)(X + (size_t)(m0 + row_) * NN_NODES  \
                                             + k0 + p_ * 4);                     \
            uint32_t dst_ = stg_ + (uint32_t)(row_ * AP + p_ * 16);              \
            int sz_ = ((m0 + row_) < NN_NODES && (k0 + p_ * 4) < NN_NODES) ? 16 : 0; \
            CP16Z(dst_, src_, sz_);                                              \
        }                                                                        \
        {                                                                        \
            uint32_t dsth = stg_ + 20480u + (uint32_t)(blr * PITCH + blh * 32);  \
            const char* sh_ = bhsrc + (size_t)(n0g + blr) * brow + k0 * 2 + blh * 32; \
            const char* sl_ = blsrc + (size_t)(n0g + blr) * brow + k0 * 2 + blh * 32; \
            CP16(dsth,          sh_);   CP16(dsth + 16,          sh_ + 16);      \
            CP16(dsth + 10240u, sl_);   CP16(dsth + 10240u + 16, sl_ + 16);      \
        }                                                                        \
    } while (0)

        // prologue: issue stage 0
        ISSUE(cst, 0); CP_COMMIT();

        for (int c = cst; c < cend; ++c) {
            const int i = c - cst;
            CP_WAIT0();
            __syncthreads();
            if (c + 1 < cend) ISSUE(c + 1, (i + 1) & 1);
            CP_COMMIT();

            const uint32_t As = sb + (uint32_t)(i & 1) * STG;
            const uint32_t Bs = As + 20480u;
#pragma unroll
            for (int ks = 0; ks < 2; ++ks) {
                const int kb = ks * 16;
                uint32_t ah[2][4], al[2][4];
                // A frags: LDS fp32 pairs in a-frag layout, truncation split
#pragma unroll
                for (int mt = 0; mt < 2; ++mt)
#pragma unroll
                    for (int j = 0; j < 4; ++j) {
                        int row = warp_m + mt * 16 + ((j & 1) << 3) + (lane >> 2);
                        int kk  = kb + ((j >> 1) << 3) + ((lane & 3) << 1);
                        float x0, x1;
                        asm volatile("ld.shared.v2.f32 {%0,%1}, [%2];"
                                     : "=f"(x0), "=f"(x1)
                                     : "r"(As + (uint32_t)(row * AP + kk * 4)));
                        uint32_t u0 = __float_as_uint(x0), u1 = __float_as_uint(x1);
                        uint32_t hi;
                        asm("prmt.b32 %0, %1, %2, 0x7632;" : "=r"(hi) : "r"(u0), "r"(u1));
                        float h0 = __uint_as_float(u0 & 0xFFFF0000u);
                        float h1 = __uint_as_float(u1 & 0xFFFF0000u);
                        float l0 = x0 - h0, l1 = x1 - h1;
                        uint32_t lo;
                        asm("cvt.rn.bf16x2.f32 %0, %1, %2;" : "=r"(lo) : "f"(l1), "f"(l0));
                        ah[mt][j] = hi;
                        al[mt][j] = lo;
                    }
                // B frags streamed per 16-col group (keeps registers low)
#pragma unroll
                for (int bb = 0; bb < 4; ++bb) {
                    uint32_t bh[4], bl[4];
                    uint32_t rb = Bs + (uint32_t)((warp_n + bb * 16 + b_noff) * PITCH
                                                  + (kb + b_koff) * 2);
                    ldm_x4(bh[0], bh[1], bh[2], bh[3], rb);
                    ldm_x4(bl[0], bl[1], bl[2], bl[3], rb + 10240u);
#pragma unroll
                    for (int mt = 0; mt < 2; ++mt)
#pragma unroll
                        for (int hf = 0; hf < 2; ++hf) {
                            int nt = bb * 2 + hf;
                            mma16816(acc[mt][nt], ah[mt], &bh[hf * 2]);
                            mma16816(acc[mt][nt], ah[mt], &bl[hf * 2]);
                            mma16816(acc[mt][nt], al[mt], &bh[hf * 2]);
                        }
                }
            }
        }
#undef ISSUE

        // drain before reusing stages in the next segment
        CP_WAIT0();
        __syncthreads();

        // segment epilogue: accumulate partial into pre-zeroed P
        {
            const int gg = lane >> 2;
            const int t2 = (lane & 3) * 2;
#pragma unroll
            for (int nt = 0; nt < 8; ++nt) {
                int n = n0g + warp_n + nt * 8 + t2;
#pragma unroll
                for (int mt = 0; mt < 2; ++mt) {
                    int ma = m0 + warp_m + mt * 16 + gg;
                    if (ma < NN_NODES) {
                        atomicAdd(&P[(size_t)ma * 256 + n],     acc[mt][nt][0]);
                        atomicAdd(&P[(size_t)ma * 256 + n + 1], acc[mt][nt][1]);
                    }
                    int mb = ma + 8;
                    if (mb < NN_NODES) {
                        atomicAdd(&P[(size_t)mb * 256 + n],     acc[mt][nt][2]);
                        atomicAdd(&P[(size_t)mb * 256 + n + 1], acc[mt][nt][3]);
                    }
                }
            }
        }
        g += (long)(cend - cst);
    }
}

// h = relu(h + bias)  (in place)
__global__ void k_combine(const float* __restrict__ bt, float* __restrict__ H) {
    int i = blockIdx.x * blockDim.x + threadIdx.x;   // float4 index
    if (i < NN_NODES * IN_C / 4) {
        float4 a = reinterpret_cast<const float4*>(H)[i];
        int col = (i * 4) & 255;
        float4 o;
        o.x = fmaxf(a.x + bt[col + 0], 0.f);
        o.y = fmaxf(a.y + bt[col + 1], 0.f);
        o.z = fmaxf(a.z + bt[col + 2], 0.f);
        o.w = fmaxf(a.w + bt[col + 3], 0.f);
        reinterpret_cast<float4*>(H)[i] = o;
    }
}

// ---------------- SpMM: one block per dst row, one thread per channel -------
template <int CH>
__global__ void __launch_bounds__(CH) k_spmm(const float* __restrict__ h,
                                             float* __restrict__ tx) {
    int d = blockIdx.x;
    int c = threadIdx.x;
    int beg = g_rowstart[d];
    int end = g_rowstart[d + 1];
    float acc = 0.0f;
    int j = beg;
    for (; j + 4 <= end; j += 4) {
        int   s0 = g_srcs[j],   s1 = g_srcs[j+1], s2 = g_srcs[j+2], s3 = g_srcs[j+3];
        float w0 = g_ws[j],     w1 = g_ws[j+1],   w2 = g_ws[j+2],   w3 = g_ws[j+3];
        float h0 = h[(size_t)s0 * CH + c];
        float h1 = h[(size_t)s1 * CH + c];
        float h2 = h[(size_t)s2 * CH + c];
        float h3 = h[(size_t)s3 * CH + c];
        acc += w0 * h0; acc += w1 * h1; acc += w2 * h2; acc += w3 * h3;
    }
    for (; j < end; ++j)
        acc += g_ws[j] * h[(size_t)g_srcs[j] * CH + c];
    tx[(size_t)d * CH + c] = acc;
}

// ---------------- SIMT SGEMM for gemm2 --------------------------------------
template <int BM, int BN, int BK, int TM, int TN, bool RELU>
__global__ void __launch_bounds__((BM / TM) * (BN / TN))
k_gemm(const float* __restrict__ A1, const float* __restrict__ B1,
       const float* __restrict__ A2, const float* __restrict__ B2,
       const float* __restrict__ bias, float* __restrict__ C,
       int M, int N, int K) {
    constexpr int NT = (BM / TM) * (BN / TN);
    __shared__ float As[BK][BM];
    __shared__ float Bs[BK][BN];

    const int tid = threadIdx.x;
    const int m0 = blockIdx.y * BM;
    const int n0 = blockIdx.x * BN;
    const int tr = tid / (BN / TN);
    const int tc = tid % (BN / TN);
    const int rowBase = tr * TM;
    const int colBase = tc * TN;

    float acc[TM][TN];
#pragma unroll
    for (int i = 0; i < TM; i++)
#pragma unroll
        for (int j = 0; j < TN; j++) acc[i][j] = 0.0f;

    const int nphase = (A2 != nullptr) ? 2 : 1;
    for (int phase = 0; phase < nphase; ++phase) {
        const float* __restrict__ A = phase ? A2 : A1;
        const float* __restrict__ B = phase ? B2 : B1;
        for (int k0 = 0; k0 < K; k0 += BK) {
            constexpr int AIT = (BM * BK / 4) / NT;
#pragma unroll
            for (int it = 0; it < AIT; ++it) {
                int idx = tid + it * NT;
                int ar = idx / (BK / 4);
                int akg = idx % (BK / 4);
                int grow = m0 + ar;
                float4 f = make_float4(0.f, 0.f, 0.f, 0.f);
                if (grow < M)
                    f = *reinterpret_cast<const float4*>(A + (size_t)grow * K + k0 + akg * 4);
                As[akg * 4 + 0][ar] = f.x;
                As[akg * 4 + 1][ar] = f.y;
                As[akg * 4 + 2][ar] = f.z;
                As[akg * 4 + 3][ar] = f.w;
            }
            constexpr int BIT = (BK * BN) / NT;
#pragma unroll
            for (int it = 0; it < BIT; ++it) {
                int idx = tid + it * NT;
                int br = idx / BN;
                int bc = idx % BN;
                Bs[br][bc] = B[(size_t)(k0 + br) * N + n0 + bc];
            }
            __syncthreads();
#pragma unroll
            for (int k = 0; k < BK; k++) {
                float ra[TM], rb[TN];
#pragma unroll
                for (int i = 0; i < TM; i++) ra[i] = As[k][rowBase + i];
#pragma unroll
                for (int j = 0; j < TN; j++) rb[j] = Bs[k][colBase + j];
#pragma unroll
                for (int i = 0; i < TM; i++)
#pragma unroll
                    for (int j = 0; j < TN; j++)
                        acc[i][j] += ra[i] * rb[j];
            }
            __syncthreads();
        }
    }

    float bv[TN];
#pragma unroll
    for (int j = 0; j < TN; j++) bv[j] = bias[n0 + colBase + j];

#pragma unroll
    for (int i = 0; i < TM; i++) {
        int grow = m0 + rowBase + i;
        if (grow < M) {
            float4 o;
            float v0 = acc[i][0] + bv[0];
            float v1 = acc[i][1] + bv[1];
            float v2 = acc[i][2] + bv[2];
            float v3 = acc[i][3] + bv[3];
            if (RELU) {
                v0 = fmaxf(v0, 0.f); v1 = fmaxf(v1, 0.f);
                v2 = fmaxf(v2, 0.f); v3 = fmaxf(v3, 0.f);
            }
            o.x = v0; o.y = v1; o.z = v2; o.w = v3;
            *reinterpret_cast<float4*>(C + (size_t)grow * N + n0 + colBase) = o;
        }
    }
}

// ---------------- fused mu+logstd GEMM (shared A tiles) ---------------------
__global__ void __launch_bounds__(256)
k_gemm_dual(const float* __restrict__ A1, const float* __restrict__ A2,
            const float* __restrict__ Bm1, const float* __restrict__ Bm2,
            const float* __restrict__ Bl1, const float* __restrict__ Bl2,
            const float* __restrict__ bm, const float* __restrict__ bl,
            float* __restrict__ Cm, float* __restrict__ Cl) {
    __shared__ float As[8][64];
    __shared__ float Bmu[8][64];
    __shared__ float Bls[8][64];
    const int tid = threadIdx.x;
    const int m0 = blockIdx.x * 64;
    const int tr = tid >> 4, tc = tid & 15;

    float am[4][4], al_[4][4];
#pragma unroll
    for (int i = 0; i < 4; i++)
#pragma unroll
        for (int j = 0; j < 4; j++) { am[i][j] = 0.f; al_[i][j] = 0.f; }

    for (int ph = 0; ph < 2; ++ph) {
        const float* A   = ph ? A2  : A1;
        const float* Bm_ = ph ? Bm2 : Bm1;
        const float* Bl_ = ph ? Bl2 : Bl1;
        for (int k0 = 0; k0 < C1; k0 += 8) {
#pragma unroll
            for (int it = 0; it < 2; ++it) {
                int idx = tid + it * 256;
                int ar = idx >> 3, ak = idx & 7;
                int gm = m0 + ar;
                As[ak][ar] = (gm < NN_NODES) ? A[(size_t)gm * C1 + k0 + ak] : 0.f;
            }
#pragma unroll
            for (int it = 0; it < 2; ++it) {
                int idx = tid + it * 256;
                int bk = idx >> 6, bc = idx & 63;
                Bmu[bk][bc] = Bm_[(size_t)(k0 + bk) * 64 + bc];
                Bls[bk][bc] = Bl_[(size_t)(k0 + bk) * 64 + bc];
            }
            __syncthreads();
#pragma unroll
            for (int k = 0; k < 8; ++k) {
                float ra[4], rm[4], rl[4];
#pragma unroll
                for (int i = 0; i < 4; i++) {
                    ra[i] = As[k][tr * 4 + i];
                    rm[i] = Bmu[k][tc * 4 + i];
                    rl[i] = Bls[k][tc * 4 + i];
                }
#pragma unroll
                for (int i = 0; i < 4; i++)
#pragma unroll
                    for (int j = 0; j < 4; j++) {
                        am[i][j]  += ra[i] * rm[j];
                        al_[i][j] += ra[i] * rl[j];
                    }
            }
            __syncthreads();
        }
    }

    float bvm[4], bvl[4];
#pragma unroll
    for (int j = 0; j < 4; j++) { bvm[j] = bm[tc * 4 + j]; bvl[j] = bl[tc * 4 + j]; }
#pragma unroll
    for (int i = 0; i < 4; i++) {
        int gm = m0 + tr * 4 + i;
        if (gm < NN_NODES) {
            float4 om, ol;
            om.x = am[i][0] + bvm[0]; om.y = am[i][1] + bvm[1];
            om.z = am[i][2] + bvm[2]; om.w = am[i][3] + bvm[3];
            ol.x = al_[i][0] + bvl[0]; ol.y = al_[i][1] + bvl[1];
            ol.z = al_[i][2] + bvl[2]; ol.w = al_[i][3] + bvl[3];
            *reinterpret_cast<float4*>(Cm + (size_t)gm * 64 + tc * 4) = om;
            *reinterpret_cast<float4*>(Cl + (size_t)gm * 64 + tc * 4) = ol;
        }
    }
}

// ---------------- launcher --------------------------------------------------
extern "C" void kernel_launch(void* const* d_in, const int* in_sizes, int n_in,
                              void* d_out, int out_size) {
    const float* x    = (const float*)d_in[0];
    const int*   ei   = (const int*)d_in[1];
    const float* Wt   = (const float*)d_in[2];
    const float* bt   = (const float*)d_in[3];
    const float* W0_1 = (const float*)d_in[4];
    const float* W1_1 = (const float*)d_in[5];
    const float* b1   = (const float*)d_in[6];
    const float* W0mu = (const float*)d_in[7];
    const float* W1mu = (const float*)d_in[8];
    const float* bmu  = (const float*)d_in[9];
    const float* W0ls = (const float*)d_in[10];
    const float* W1ls = (const float*)d_in[11];
    const float* bls  = (const float*)d_in[12];
    float* out = (float*)d_out;

    float *h, *tx1, *h2, *tx2;
    cudaGetSymbolAddress((void**)&h,   g_h);
    cudaGetSymbolAddress((void**)&tx1, g_tx1);
    cudaGetSymbolAddress((void**)&h2,  g_h2);
    cudaGetSymbolAddress((void**)&tx2, g_tx2);

    cudaFuncSetAttribute(k_gemm1_mma, cudaFuncAttributeMaxDynamicSharedMemorySize, G1_SMEM);

    const int TPB = 256;

    // GEMM1 deps first; k_gemm1_mma stays at launch index 3 (ncu samples it)
    {
        dim3 grid(KPAD / 32, 256 / 32), blk(32, 32);
        k_convW<<<grid, blk>>>(Wt);                                  // 0
    }
    k_zeroH<<<(NN_NODES * IN_C / 4 + TPB - 1) / TPB, TPB>>>();       // 1
    k_zero_deg<<<(NN_NODES + TPB - 1) / TPB, TPB>>>(NN_NODES);       // 2
    k_gemm1_mma<<<NCTAS, 256, G1_SMEM>>>(x, h);                      // 3
    k_combine<<<(NN_NODES * IN_C / 4 + TPB - 1) / TPB, TPB>>>(bt, h);
    k_count<<<(NE + TPB - 1) / TPB, TPB>>>(ei);
    k_dinv<<<(NN_NODES + TPB - 1) / TPB, TPB>>>(NN_NODES);
    k_scan<<<1, 1024>>>(NN_NODES);
    k_bucket<<<(NE + TPB - 1) / TPB, TPB>>>(ei);

    // tx1 = L_hat @ h
    k_spmm<IN_C><<<NN_NODES, IN_C>>>(h, tx1);

    // h2 = relu(h @ W0_1 + tx1 @ W1_1 + b1)
    {
        dim3 grid(C1 / 64, (NN_NODES + 127) / 128);
        k_gemm<128, 64, 8, 8, 4, true><<<grid, 256>>>(
            h, W0_1, tx1, W1_1, b1, h2, NN_NODES, C1, IN_C);
    }
    // tx2 = L_hat @ h2
    k_spmm<C1><<<NN_NODES, C1>>>(h2, tx2);

    // mu / logstd fused
    k_gemm_dual<<<157, 256>>>(h2, tx2, W0mu, W1mu, W0ls, W1ls,
                              bmu, bls, out, out + (size_t)NN_NODES * OUT_C);
}